// round 2
// baseline (speedup 1.0000x reference)
#include <cuda_runtime.h>
#include <math.h>

// Problem-fixed maxima
#define MAXN 100096
#define MAXE 1600000
#define F    128

// ---------------- device scratch (no runtime allocation allowed) -------------
__device__ int   g_cnt[MAXN];
__device__ int   g_rowptr[MAXN + 1];
__device__ int   g_cursor[MAXN];
__device__ int   g_col[MAXE];
__device__ int   g_bsum[256];
__device__ float g_dis[MAXN];

__device__ float g_t0[MAXN * F];
__device__ float g_t1[MAXN * F];
__device__ float g_env[MAXN * F];
__device__ float g_inv[MAXN * F];
__device__ float g_dec[MAXN * F];

// CKA moment buffer: Sxx[16384] | Sxy[16384] | Syy[16384] | sx[128] | sy[128]
#define CKA_SXX 0
#define CKA_SXY 16384
#define CKA_SYY 32768
#define CKA_SX  49152
#define CKA_SY  49280
#define CKA_TOT 49408
__device__ float g_cka[CKA_TOT];

// ---------------- graph prep -------------------------------------------------
__global__ void k_zero_cnt(int n) {
    int i = blockIdx.x * blockDim.x + threadIdx.x;
    if (i < n) g_cnt[i] = 0;
}

__global__ void k_zero_f(float* p, int n) {
    int i = blockIdx.x * blockDim.x + threadIdx.x;
    if (i < n) p[i] = 0.f;
}

__global__ void k_count(const int* __restrict__ ei, int E) {
    int e = blockIdx.x * blockDim.x + threadIdx.x;
    if (e < E) atomicAdd(&g_cnt[ei[E + e]], 1);
}

__global__ void k_dis(int n) {
    int v = blockIdx.x * blockDim.x + threadIdx.x;
    if (v < n) g_dis[v] = rsqrtf((float)(g_cnt[v] + 1));  // +1 self loop
}

// block-sum of cnt per 1024-chunk
__global__ void k_breduce(int n) {
    __shared__ int s[1024];
    int t = threadIdx.x;
    int i = blockIdx.x * 1024 + t;
    s[t] = (i < n) ? g_cnt[i] : 0;
    __syncthreads();
    for (int off = 512; off > 0; off >>= 1) {
        if (t < off) s[t] += s[t + off];
        __syncthreads();
    }
    if (t == 0) g_bsum[blockIdx.x] = s[0];
}

__global__ void k_bscan(int nb, int n) {
    if (threadIdx.x == 0 && blockIdx.x == 0) {
        int acc = 0;
        for (int i = 0; i < nb; ++i) { int v = g_bsum[i]; g_bsum[i] = acc; acc += v; }
        g_rowptr[n] = acc;   // == E
    }
}

__global__ void k_scan(int n) {
    __shared__ int s[1024];
    int t = threadIdx.x;
    int i = blockIdx.x * 1024 + t;
    int v = (i < n) ? g_cnt[i] : 0;
    s[t] = v;
    __syncthreads();
    for (int off = 1; off < 1024; off <<= 1) {
        int u = (t >= off) ? s[t - off] : 0;
        __syncthreads();
        s[t] += u;
        __syncthreads();
    }
    int ex = s[t] - v + g_bsum[blockIdx.x];
    if (i < n) { g_rowptr[i] = ex; g_cursor[i] = ex; }
}

__global__ void k_fill(const int* __restrict__ ei, int E) {
    int e = blockIdx.x * blockDim.x + threadIdx.x;
    if (e < E) {
        int src = ei[e];
        int dst = ei[E + e];
        int p = atomicAdd(&g_cursor[dst], 1);
        g_col[p] = src;
    }
}

// ---------------- GEMM: out[row] (+)= dis[row] * (A[row,:K] @ W[K,128]) ------
__global__ __launch_bounds__(256)
void k_gemm(const float* __restrict__ A, const float* __restrict__ W,
            const float* __restrict__ dis, float* __restrict__ out,
            int n, int K, int accumulate)
{
    __shared__ float As[16][132];   // [k][m], padded (528B rows, 16B aligned)
    __shared__ float Bs[16][128];   // [k][col]
    const int tid = threadIdx.x;
    const int ty = tid >> 4;        // 0..15
    const int tx = tid & 15;        // 0..15
    const int br = blockIdx.x * 128;

    float c[8][8];
#pragma unroll
    for (int i = 0; i < 8; ++i)
#pragma unroll
        for (int j = 0; j < 8; ++j) c[i][j] = 0.f;

    for (int k0 = 0; k0 < K; k0 += 16) {
#pragma unroll
        for (int i = 0; i < 8; ++i) {
            int idx = tid + i * 256;       // 0..2047
            int m = idx >> 4;
            int k = idx & 15;
            int row = br + m;
            As[k][m] = (row < n) ? A[row * K + k0 + k] : 0.f;
        }
#pragma unroll
        for (int i = 0; i < 8; ++i) {
            int idx = tid + i * 256;
            int k = idx >> 7;
            int cc = idx & 127;
            Bs[k][cc] = W[(k0 + k) * 128 + cc];
        }
        __syncthreads();
#pragma unroll
        for (int k = 0; k < 16; ++k) {
            float4 a0 = *(const float4*)&As[k][ty * 4];
            float4 a1 = *(const float4*)&As[k][64 + ty * 4];
            float4 b0 = *(const float4*)&Bs[k][tx * 4];
            float4 b1 = *(const float4*)&Bs[k][64 + tx * 4];
            float av[8] = {a0.x, a0.y, a0.z, a0.w, a1.x, a1.y, a1.z, a1.w};
            float bv[8] = {b0.x, b0.y, b0.z, b0.w, b1.x, b1.y, b1.z, b1.w};
#pragma unroll
            for (int i = 0; i < 8; ++i)
#pragma unroll
                for (int j = 0; j < 8; ++j) c[i][j] = fmaf(av[i], bv[j], c[i][j]);
        }
        __syncthreads();
    }

#pragma unroll
    for (int ih = 0; ih < 2; ++ih)
#pragma unroll
        for (int i = 0; i < 4; ++i) {
            int row = br + ih * 64 + ty * 4 + i;
            if (row >= n) continue;
            float d = dis ? dis[row] : 1.f;
#pragma unroll
            for (int jh = 0; jh < 2; ++jh) {
                float* p = &out[row * 128 + jh * 64 + tx * 4];
                float4 v;
                v.x = d * c[ih * 4 + i][jh * 4 + 0];
                v.y = d * c[ih * 4 + i][jh * 4 + 1];
                v.z = d * c[ih * 4 + i][jh * 4 + 2];
                v.w = d * c[ih * 4 + i][jh * 4 + 3];
                if (accumulate) {
                    float4 o = *(const float4*)p;
                    v.x += o.x; v.y += o.y; v.z += o.z; v.w += o.w;
                }
                *(float4*)p = v;
            }
        }
}

// ---------------- AGG: out[v] = act(dis[v]*(sum_{u->v} hp[u] + hp[v]) + b) ---
__global__ void k_agg(const float* __restrict__ hp, const float* __restrict__ bias,
                      float* __restrict__ out, int n, int act)
{
    int gw = (blockIdx.x * blockDim.x + threadIdx.x) >> 5;
    int lane = threadIdx.x & 31;
    if (gw >= n) return;
    const float4* h4 = (const float4*)hp;
    float4 a = h4[gw * 32 + lane];                 // self loop term (hp = dis*XW)
    int s = g_rowptr[gw], e = g_rowptr[gw + 1];
    for (int i = s; i < e; ++i) {
        int u = g_col[i];
        float4 v = __ldg(&h4[u * 32 + lane]);
        a.x += v.x; a.y += v.y; a.z += v.z; a.w += v.w;
    }
    float d = g_dis[gw];
    float4 b = ((const float4*)bias)[lane];
    float4 r;
    r.x = fmaf(d, a.x, b.x);
    r.y = fmaf(d, a.y, b.y);
    r.z = fmaf(d, a.z, b.z);
    r.w = fmaf(d, a.w, b.w);
    if (act == 1) {
        r.x = fmaxf(r.x, 0.f); r.y = fmaxf(r.y, 0.f);
        r.z = fmaxf(r.z, 0.f); r.w = fmaxf(r.w, 0.f);
    } else if (act == 2) {
        r.x = tanhf(r.x); r.y = tanhf(r.y);
        r.z = tanhf(r.z); r.w = tanhf(r.w);
    }
    ((float4*)out)[gw * 32 + lane] = r;
}

// ---------------- LayerNorm row-wise ------------------------------------------
__global__ void k_ln(const float* __restrict__ dec, const float* __restrict__ g,
                     const float* __restrict__ b, float* __restrict__ out, int n)
{
    int gw = (blockIdx.x * blockDim.x + threadIdx.x) >> 5;
    int lane = threadIdx.x & 31;
    if (gw >= n) return;
    float4 v = ((const float4*)dec)[gw * 32 + lane];
    float s = v.x + v.y + v.z + v.w;
#pragma unroll
    for (int o = 16; o; o >>= 1) s += __shfl_xor_sync(0xffffffffu, s, o);
    float mu = s * (1.f / 128.f);
    float dx = v.x - mu, dy = v.y - mu, dz = v.z - mu, dw = v.w - mu;
    float q = dx * dx + dy * dy + dz * dz + dw * dw;
#pragma unroll
    for (int o = 16; o; o >>= 1) q += __shfl_xor_sync(0xffffffffu, q, o);
    float rs = rsqrtf(q * (1.f / 128.f) + 1e-5f);
    float4 gg = ((const float4*)g)[lane];
    float4 bb = ((const float4*)b)[lane];
    float* o = out + (size_t)gw * 128 + lane * 4;   // out may be misaligned by +1
    o[0] = dx * rs * gg.x + bb.x;
    o[1] = dy * rs * gg.y + bb.y;
    o[2] = dz * rs * gg.z + bb.z;
    o[3] = dw * rs * gg.w + bb.w;
}

// ---------------- CKA moments --------------------------------------------------
__global__ void k_colsum(const float* __restrict__ X, float* __restrict__ s, int n)
{
    int j = threadIdx.x;   // 128 threads
    int r0 = blockIdx.x * 256;
    int r1 = r0 + 256; if (r1 > n) r1 = n;
    float acc = 0.f;
    for (int r = r0; r < r1; ++r) acc += X[r * 128 + j];
    atomicAdd(&s[j], acc);
}

__global__ __launch_bounds__(256)
void k_atb(const float* __restrict__ X, const float* __restrict__ Y,
           float* __restrict__ S, int n)
{
    __shared__ float Xs[32][128];
    __shared__ float Ys[32][128];
    const int tid = threadIdx.x;
    const int ty = tid >> 4;
    const int tx = tid & 15;
    float c[8][8];
#pragma unroll
    for (int i = 0; i < 8; ++i)
#pragma unroll
        for (int j = 0; j < 8; ++j) c[i][j] = 0.f;

    for (int base = blockIdx.x * 32; base < n; base += gridDim.x * 32) {
#pragma unroll
        for (int i = 0; i < 16; ++i) {
            int idx = tid + i * 256;
            int r = idx >> 7, f = idx & 127;
            int row = base + r;
            Xs[r][f] = (row < n) ? X[row * 128 + f] : 0.f;
        }
#pragma unroll
        for (int i = 0; i < 16; ++i) {
            int idx = tid + i * 256;
            int r = idx >> 7, f = idx & 127;
            int row = base + r;
            Ys[r][f] = (row < n) ? Y[row * 128 + f] : 0.f;
        }
        __syncthreads();
#pragma unroll
        for (int r = 0; r < 32; ++r) {
            float4 a0 = *(const float4*)&Xs[r][ty * 4];
            float4 a1 = *(const float4*)&Xs[r][64 + ty * 4];
            float4 b0 = *(const float4*)&Ys[r][tx * 4];
            float4 b1 = *(const float4*)&Ys[r][64 + tx * 4];
            float av[8] = {a0.x, a0.y, a0.z, a0.w, a1.x, a1.y, a1.z, a1.w};
            float bv[8] = {b0.x, b0.y, b0.z, b0.w, b1.x, b1.y, b1.z, b1.w};
#pragma unroll
            for (int i = 0; i < 8; ++i)
#pragma unroll
                for (int j = 0; j < 8; ++j) c[i][j] = fmaf(av[i], bv[j], c[i][j]);
        }
        __syncthreads();
    }

#pragma unroll
    for (int ih = 0; ih < 2; ++ih)
#pragma unroll
        for (int i = 0; i < 4; ++i) {
            int fi = ih * 64 + ty * 4 + i;
#pragma unroll
            for (int jh = 0; jh < 2; ++jh)
#pragma unroll
                for (int j = 0; j < 4; ++j) {
                    int fj = jh * 64 + tx * 4 + j;
                    atomicAdd(&S[fi * 128 + fj], c[ih * 4 + i][jh * 4 + j]);
                }
        }
}

__global__ void k_cka(const float* __restrict__ cka, float* __restrict__ out,
                      int off, float fn)
{
    __shared__ float r0[256], r1[256], r2[256];
    const float* Sxx = cka + CKA_SXX;
    const float* Sxy = cka + CKA_SXY;
    const float* Syy = cka + CKA_SYY;
    const float* sx  = cka + CKA_SX;
    const float* sy  = cka + CKA_SY;
    int t = threadIdx.x;
    float hs = 0.f, nx = 0.f, ny = 0.f;
    float inv_n = 1.f / fn;
    for (int idx = t; idx < 16384; idx += 256) {
        int i = idx >> 7, j = idx & 127;
        float mxi = sx[i] * inv_n, mxj = sx[j] * inv_n;
        float myi = sy[i] * inv_n, myj = sy[j] * inv_n;
        float cxy = Sxy[idx] - fn * mxi * myj;
        float cxx = Sxx[idx] - fn * mxi * mxj;
        float cyy = Syy[idx] - fn * myi * myj;
        hs += cxy * cxy;
        nx += cxx * cxx;
        ny += cyy * cyy;
    }
    r0[t] = hs; r1[t] = nx; r2[t] = ny;
    __syncthreads();
    for (int o = 128; o > 0; o >>= 1) {
        if (t < o) { r0[t] += r0[t + o]; r1[t] += r1[t + o]; r2[t] += r2[t + o]; }
        __syncthreads();
    }
    if (t == 0) {
        float val = r0[0] / (sqrtf(r1[0]) * sqrtf(r2[0]));
        for (int i = 0; i < off; ++i) out[i] = val;
    }
}

// ---------------- host ----------------------------------------------------------
extern "C" void kernel_launch(void* const* d_in, const int* in_sizes, int n_in,
                              void* d_out, int out_size)
{
    const float* x     = (const float*)d_in[0];
    const int*   ei    = (const int*)  d_in[1];
    const float* W_ir1 = (const float*)d_in[2];
    const float* b_ir1 = (const float*)d_in[3];
    const float* W_ir2 = (const float*)d_in[4];
    const float* b_ir2 = (const float*)d_in[5];
    const float* W_g1  = (const float*)d_in[6];
    const float* b_g1  = (const float*)d_in[7];
    const float* W_g2  = (const float*)d_in[8];
    const float* b_g2  = (const float*)d_in[9];
    const float* W_d1  = (const float*)d_in[10];
    const float* b_d1  = (const float*)d_in[11];
    const float* W_d2  = (const float*)d_in[12];
    const float* b_d2  = (const float*)d_in[13];
    const float* ln_g  = (const float*)d_in[14];
    const float* ln_b  = (const float*)d_in[15];
    // d_in[16] = step (always 3) — unused

    const int N = in_sizes[0] / F;
    const int E = in_sizes[1] / 2;

    float *t0, *t1, *envp, *invp, *decp, *disp, *cka;
    cudaGetSymbolAddress((void**)&t0,   g_t0);
    cudaGetSymbolAddress((void**)&t1,   g_t1);
    cudaGetSymbolAddress((void**)&envp, g_env);
    cudaGetSymbolAddress((void**)&invp, g_inv);
    cudaGetSymbolAddress((void**)&decp, g_dec);
    cudaGetSymbolAddress((void**)&disp, g_dis);
    cudaGetSymbolAddress((void**)&cka,  g_cka);

    // ---- CSR build + symmetric-norm scaling -------------------------------
    k_zero_cnt<<<(N + 255) / 256, 256>>>(N);
    k_count<<<(E + 255) / 256, 256>>>(ei, E);
    k_dis<<<(N + 255) / 256, 256>>>(N);
    int NB = (N + 1023) / 1024;
    k_breduce<<<NB, 1024>>>(N);
    k_bscan<<<1, 32>>>(NB, N);
    k_scan<<<NB, 1024>>>(N);
    k_fill<<<(E + 255) / 256, 256>>>(ei, E);

    const int gb = (N + 127) / 128;
    const int aw = (N * 32 + 255) / 256;

    // ---- ir_Learner: env = tanh(gcn2(x; W_ir1,W_ir2)) ----------------------
    k_gemm<<<gb, 256>>>(x,  W_ir1, disp, t0, N, 128, 0);
    k_agg <<<aw, 256>>>(t0, b_ir1, t1, N, 1);
    k_gemm<<<gb, 256>>>(t1, W_ir2, disp, t0, N, 128, 0);
    k_agg <<<aw, 256>>>(t0, b_ir2, envp, N, 2);

    // ---- main gnn: inv = gcn2(x; W_g1,W_g2) --------------------------------
    k_gemm<<<gb, 256>>>(x,  W_g1, disp, t0, N, 128, 0);
    k_agg <<<aw, 256>>>(t0, b_g1, t1, N, 1);
    k_gemm<<<gb, 256>>>(t1, W_g2, disp, t0, N, 128, 0);
    k_agg <<<aw, 256>>>(t0, b_g2, invp, N, 0);

    // ---- decoder: gcn2(concat(env,inv); W_d1,W_d2) -------------------------
    k_gemm<<<gb, 256>>>(envp, W_d1,             disp, t0, N, 128, 0);
    k_gemm<<<gb, 256>>>(invp, W_d1 + 128 * 128, disp, t0, N, 128, 1);
    k_agg <<<aw, 256>>>(t0, b_d1, t1, N, 1);
    k_gemm<<<gb, 256>>>(t1, W_d2, disp, t0, N, 128, 0);
    k_agg <<<aw, 256>>>(t0, b_d2, decp, N, 0);

    // ---- LayerNorm -> rebuilt (tail of d_out) ------------------------------
    float* out = (float*)d_out;
    int off = out_size - N * F;   // scalar (ind_loss) lives at the head
    if (off < 0) off = 0;
    k_ln<<<aw, 256>>>(decp, ln_g, ln_b, out + off, N);

    // ---- linear CKA(env, inv) -> out[0] ------------------------------------
    k_zero_f<<<(CKA_TOT + 255) / 256, 256>>>(cka, CKA_TOT);
    k_colsum<<<(N + 255) / 256, 128>>>(envp, cka + CKA_SX, N);
    k_colsum<<<(N + 255) / 256, 128>>>(invp, cka + CKA_SY, N);
    k_atb<<<148, 256>>>(envp, envp, cka + CKA_SXX, N);
    k_atb<<<148, 256>>>(envp, invp, cka + CKA_SXY, N);
    k_atb<<<148, 256>>>(invp, invp, cka + CKA_SYY, N);
    k_cka<<<1, 256>>>(cka, out, off > 0 ? off : 1, (float)N);
}